// round 10
// baseline (speedup 1.0000x reference)
#include <cuda_runtime.h>
#include <cuda_bf16.h>
#include <math.h>
#include <cstdint>

#define NN   50000
#define EE   800000
#define HH   128
#define GG   64
#define LL   6
#define OUTC 10
#define EPS  1e-5f
#define NPART 98            // ceil(NN/512)
#define TILES ((NN + 63) / 64)
#define GEMM_GRID 148       // 1 CTA/SM persistent
#define BP   136            // bf16 smem pitch (272B rows)
#define SP   132            // fp32 staging pitch (528B rows)

typedef unsigned long long ull;

// ---------------- scratch (device globals) ----------------------------------
__device__ float g_buf [NN * HH];
__device__ float g_lin [NN * HH];
__device__ int   g_cnt [NN];
__device__ int   g_cur [NN];
__device__ int   g_rowptr[NN + 1];
__device__ int   g_part[NPART];
__device__ int   g_col [EE];
__device__ float g_wgt [EE];
__device__ float g_dinv[NN];
__device__ float g_selfw[NN];
__device__ float g_stats[(LL - 1) * 2 * HH];
__device__ float g_pooled[GG * HH];
__device__ float g_z1[GG * HH];
__device__ float g_z2[GG * HH];

// ---------------- mma / ldmatrix / cp.async helpers --------------------------
__device__ __forceinline__ uint32_t smem_u32(const void* p) {
    uint32_t a;
    asm("{ .reg .u64 t; cvta.to.shared.u64 t, %1; cvt.u32.u64 %0, t; }" : "=r"(a) : "l"(p));
    return a;
}
__device__ __forceinline__ void ldmx4(uint32_t& r0, uint32_t& r1, uint32_t& r2,
                                      uint32_t& r3, uint32_t a) {
    asm volatile("ldmatrix.sync.aligned.m8n8.x4.shared.b16 {%0,%1,%2,%3}, [%4];"
                 : "=r"(r0), "=r"(r1), "=r"(r2), "=r"(r3) : "r"(a));
}
__device__ __forceinline__ void mma_bf16(float* c, const uint32_t* a,
                                         uint32_t b0, uint32_t b1) {
    asm volatile("mma.sync.aligned.m16n8k16.row.col.f32.bf16.bf16.f32 "
                 "{%0,%1,%2,%3}, {%4,%5,%6,%7}, {%8,%9}, {%0,%1,%2,%3};"
                 : "+f"(c[0]), "+f"(c[1]), "+f"(c[2]), "+f"(c[3])
                 : "r"(a[0]), "r"(a[1]), "r"(a[2]), "r"(a[3]), "r"(b0), "r"(b1));
}
__device__ __forceinline__ uint32_t pack_hi(float x, float y) {
    __nv_bfloat162 h(__float2bfloat16_rn(x), __float2bfloat16_rn(y));
    return *(uint32_t*)&h;
}
__device__ __forceinline__ uint32_t pack_lo(float x, float y) {
    __nv_bfloat16 hx = __float2bfloat16_rn(x);
    __nv_bfloat16 hy = __float2bfloat16_rn(y);
    __nv_bfloat162 l(__float2bfloat16_rn(x - __bfloat162float(hx)),
                     __float2bfloat16_rn(y - __bfloat162float(hy)));
    return *(uint32_t*)&l;
}
__device__ __forceinline__ void cpa16(uint32_t s, const void* g, int sz) {
    asm volatile("cp.async.cg.shared.global [%0], [%1], 16, %2;"
                 :: "r"(s), "l"(g), "r"(sz) : "memory");
}
__device__ __forceinline__ void cpa_commit() {
    asm volatile("cp.async.commit_group;" ::: "memory");
}
template <int N>
__device__ __forceinline__ void cpa_wait() {
    asm volatile("cp.async.wait_group %0;" :: "n"(N) : "memory");
}

// ---------------- graph preprocessing ---------------------------------------
__global__ void k_zero_counts() {
    int i = blockIdx.x * blockDim.x + threadIdx.x;
    if (i < NN) { g_cnt[i] = 0; g_cur[i] = 0; }
    if (i < (LL - 1) * 2 * HH) g_stats[i] = 0.f;
}

__global__ void k_hist(const int* __restrict__ dst) {
    int i = blockIdx.x * blockDim.x + threadIdx.x;
    if (i < EE) atomicAdd(&g_cnt[dst[i]], 1);
}

__global__ void k_scan_local() {
    __shared__ int sh[512];
    int t = threadIdx.x;
    int i = blockIdx.x * 512 + t;
    int v = (i < NN) ? g_cnt[i] : 0;
    sh[t] = v;
    __syncthreads();
    for (int off = 1; off < 512; off <<= 1) {
        int a = (t >= off) ? sh[t - off] : 0;
        __syncthreads();
        sh[t] += a;
        __syncthreads();
    }
    if (i < NN) g_rowptr[i + 1] = sh[t];
    if (t == 511) g_part[blockIdx.x] = sh[t];
}

__global__ void k_scan_part() {
    __shared__ int sh[128];
    int t = threadIdx.x;
    int v = (t < NPART) ? g_part[t] : 0;
    sh[t] = v;
    __syncthreads();
    for (int off = 1; off < 128; off <<= 1) {
        int a = (t >= off) ? sh[t - off] : 0;
        __syncthreads();
        sh[t] += a;
        __syncthreads();
    }
    if (t < NPART) g_part[t] = sh[t] - v;   // exclusive
}

__global__ void k_scan_add() {
    int i = blockIdx.x * blockDim.x + threadIdx.x;
    if (i < NN) g_rowptr[i + 1] += g_part[i >> 9];
    if (i == 0) g_rowptr[0] = 0;
}

__global__ void k_dinv() {
    int i = blockIdx.x * blockDim.x + threadIdx.x;
    if (i < NN) {
        float deg = (float)(g_cnt[i] + 1);
        g_dinv[i] = rsqrtf(deg);
        g_selfw[i] = 1.f / deg;
    }
}

__global__ void k_scatter(const int* __restrict__ src, const int* __restrict__ dst) {
    int i = blockIdx.x * blockDim.x + threadIdx.x;
    if (i < EE) {
        int s = src[i], d = dst[i];
        int p = atomicAdd(&g_cur[d], 1);
        int idx = g_rowptr[d] + p;
        g_col[idx] = s;
        g_wgt[idx] = g_dinv[s] * g_dinv[d];
    }
}

// ---------------- tensor-core GEMM: Y = act(X) @ W ---------------------------
// mma.sync m16n8k16 bf16, 3-pass split. Warp = 32 rows x 32 cols; B fragments
// register-resident for the CTA lifetime. X tiles arrive via cp.async into a
// double-buffered fp32 staging area (LDG latency hidden behind mma of the
// previous tile); per-tile work is a cheap smem->smem BN+split transform.
#define SM_BHI  0
#define SM_BLO  (SM_BHI + HH * BP * 2)
#define SM_XHI  (SM_BLO + HH * BP * 2)
#define SM_XLO  (SM_XHI + 64 * BP * 2)
#define SM_STG0 (SM_XLO + 64 * BP * 2)
#define SM_STG1 (SM_STG0 + 64 * SP * 4)
#define SM_SC   (SM_STG1 + 64 * SP * 4)
#define SM_SH   (SM_SC + 512)
#define SMEM_TC (SM_SH + 512)

__global__ __launch_bounds__(256, 1)
void k_gemm(const float* __restrict__ X, const float* __restrict__ W,
            float* __restrict__ Y,
            const float* __restrict__ stats,
            const float* __restrict__ gamma, const float* __restrict__ beta,
            int bn) {
    extern __shared__ char smem[];
    __nv_bfloat16* Bh = (__nv_bfloat16*)(smem + SM_BHI);
    __nv_bfloat16* Bl = (__nv_bfloat16*)(smem + SM_BLO);
    float* sc = (float*)(smem + SM_SC);
    float* shf = (float*)(smem + SM_SH);

    int tid = threadIdx.x;
    int warp = tid >> 5, lane = tid & 31;

    uint32_t stg_u[2] = { smem_u32(smem + SM_STG0), smem_u32(smem + SM_STG1) };
    const float* stg_f[2] = { (const float*)(smem + SM_STG0), (const float*)(smem + SM_STG1) };

    // ---- prologue: issue cp.async for first tile ----
    {
        int tile0 = blockIdx.x;
        int row0 = tile0 * 64;
#pragma unroll
        for (int it = 0; it < 8; it++) {
            int row = it * 8 + warp;
            int grow = row0 + row;
            bool rv = grow < NN;
            const float* g = X + (size_t)(rv ? grow : 0) * HH + 4 * lane;
            cpa16(stg_u[0] + (uint32_t)((row * SP + 4 * lane) * 4), g, rv ? 16 : 0);
        }
        cpa_commit();
    }

    if (bn && tid < HH) {
        float mu  = stats[tid] * (1.f / NN);
        float var = stats[HH + tid] * (1.f / NN) - mu * mu;
        float s = rsqrtf(var + EPS) * gamma[tid];
        sc[tid] = s;
        shf[tid] = beta[tid] - mu * s;
    }

    {   // split W into Bt[n][k] hi/lo (once per CTA)
        const float4* W4 = (const float4*)W;
        for (int i = tid; i < HH * 32; i += 256) {
            int k = i >> 5, n4 = i & 31;
            float4 v = W4[k * 32 + n4];
            const float* vv = (const float*)&v;
#pragma unroll
            for (int j = 0; j < 4; j++) {
                int n = n4 * 4 + j;
                __nv_bfloat16 hi = __float2bfloat16_rn(vv[j]);
                Bh[n * BP + k] = hi;
                Bl[n * BP + k] = __float2bfloat16_rn(vv[j] - __bfloat162float(hi));
            }
        }
    }
    __syncthreads();

    uint32_t xh_u = smem_u32(smem + SM_XHI);
    uint32_t xl_u = smem_u32(smem + SM_XLO);
    uint32_t bh_u = smem_u32(smem + SM_BHI);
    uint32_t bl_u = smem_u32(smem + SM_BLO);

    int mrow = (warp & 1) * 32;
    int ncol = (warp >> 1) * 32;

    int aj = lane >> 3, ar = lane & 7;
    int a_rb  = ((aj & 1) << 3) + ar;
    int a_kad = (aj >> 1) << 3;
    int b_rowoff = ((aj >> 1) << 3) + ar;
    int b_kad = (aj & 1) << 3;

    // ---- preload ALL B fragments for this warp's 32 cols ----
    uint32_t bhr[8][2][4], blr[8][2][4];
#pragma unroll
    for (int ks = 0; ks < 8; ks++)
#pragma unroll
        for (int ng = 0; ng < 2; ng++) {
            int n0 = ncol + 16 * ng;
            uint32_t boff = (uint32_t)(((n0 + b_rowoff) * BP + ks * 16 + b_kad) * 2);
            ldmx4(bhr[ks][ng][0], bhr[ks][ng][1], bhr[ks][ng][2], bhr[ks][ng][3], bh_u + boff);
            ldmx4(blr[ks][ng][0], blr[ks][ng][1], blr[ks][ng][2], blr[ks][ng][3], bl_u + boff);
        }

    int cur = 0;
    for (int tile = blockIdx.x; tile < TILES; tile += gridDim.x, cur ^= 1) {
        int row0 = tile * 64;
        int ntile = tile + gridDim.x;
        bool have_next = ntile < TILES;

        if (have_next) {   // issue next tile's fill into the other buffer
            int nrow0 = ntile * 64;
#pragma unroll
            for (int it = 0; it < 8; it++) {
                int row = it * 8 + warp;
                int grow = nrow0 + row;
                bool rv = grow < NN;
                const float* g = X + (size_t)(rv ? grow : 0) * HH + 4 * lane;
                cpa16(stg_u[cur ^ 1] + (uint32_t)((row * SP + 4 * lane) * 4), g, rv ? 16 : 0);
            }
            cpa_commit();
            cpa_wait<1>();     // current buffer's group complete
        } else {
            cpa_wait<0>();
        }
        __syncthreads();       // all warps done with prev mma + staging ready

        {   // transform staging[cur] -> Xhi/Xlo (BN/ReLU fused)
            const float* stg = stg_f[cur];
#pragma unroll
            for (int it = 0; it < 8; it++) {
                int row = it * 8 + warp;
                int ch0 = 4 * lane;
                float4 v = *(const float4*)&stg[row * SP + ch0];
                if (bn) {
                    v.x = fmaxf(v.x * sc[ch0]     + shf[ch0],     0.f);
                    v.y = fmaxf(v.y * sc[ch0 + 1] + shf[ch0 + 1], 0.f);
                    v.z = fmaxf(v.z * sc[ch0 + 2] + shf[ch0 + 2], 0.f);
                    v.w = fmaxf(v.w * sc[ch0 + 3] + shf[ch0 + 3], 0.f);
                }
                uint2 hp, lp;
                hp.x = pack_hi(v.x, v.y); hp.y = pack_hi(v.z, v.w);
                lp.x = pack_lo(v.x, v.y); lp.y = pack_lo(v.z, v.w);
                *(uint2*)(smem + SM_XHI + (row * BP + ch0) * 2) = hp;
                *(uint2*)(smem + SM_XLO + (row * BP + ch0) * 2) = lp;
            }
        }
        __syncthreads();

        float c[2][2][2][4];
#pragma unroll
        for (int mg = 0; mg < 2; mg++)
#pragma unroll
            for (int ng = 0; ng < 2; ng++)
#pragma unroll
                for (int nh = 0; nh < 2; nh++)
#pragma unroll
                    for (int j = 0; j < 4; j++) c[mg][ng][nh][j] = 0.f;

#pragma unroll
        for (int ks = 0; ks < 8; ks++) {
            int k0 = ks * 16;
#pragma unroll
            for (int mg = 0; mg < 2; mg++) {
                uint32_t ahi[4], alo[4];
                uint32_t aoff = (uint32_t)(((mrow + 16 * mg + a_rb) * BP + k0 + a_kad) * 2);
                ldmx4(ahi[0], ahi[1], ahi[2], ahi[3], xh_u + aoff);
                ldmx4(alo[0], alo[1], alo[2], alo[3], xl_u + aoff);
#pragma unroll
                for (int ng = 0; ng < 2; ng++) {
                    const uint32_t* bh = bhr[ks][ng];
                    const uint32_t* bl = blr[ks][ng];
                    mma_bf16(c[mg][ng][0], ahi, bh[0], bh[1]);
                    mma_bf16(c[mg][ng][0], alo, bh[0], bh[1]);
                    mma_bf16(c[mg][ng][0], ahi, bl[0], bl[1]);
                    mma_bf16(c[mg][ng][1], ahi, bh[2], bh[3]);
                    mma_bf16(c[mg][ng][1], alo, bh[2], bh[3]);
                    mma_bf16(c[mg][ng][1], ahi, bl[2], bl[3]);
                }
            }
        }

        {   // epilogue
            int cb = 2 * (lane & 3);
            int rowin = lane >> 2;
#pragma unroll
            for (int mg = 0; mg < 2; mg++) {
                int m1 = row0 + mrow + 16 * mg + rowin;
                int m2 = m1 + 8;
                bool v1 = m1 < NN, v2 = m2 < NN;
#pragma unroll
                for (int ng = 0; ng < 2; ng++)
#pragma unroll
                    for (int nh = 0; nh < 2; nh++) {
                        int n0 = ncol + 16 * ng + 8 * nh + cb;
                        float* cc = c[mg][ng][nh];
                        if (v1) *(float2*)(Y + (size_t)m1 * HH + n0) = make_float2(cc[0], cc[1]);
                        if (v2) *(float2*)(Y + (size_t)m2 * HH + n0) = make_float2(cc[2], cc[3]);
                    }
            }
        }
    }
}

// ---------------- aggregation + fused BN stats ------------------------------
__global__ __launch_bounds__(256)
void k_agg(const float* __restrict__ hlin, const float* __restrict__ bias,
           float* __restrict__ hout, float* __restrict__ stats, int do_stats) {
    int lane = threadIdx.x & 31;
    int warp = threadIdx.x >> 5;
    int gw = blockIdx.x * 8 + warp;
    int nw = gridDim.x * 8;

    const float4* h4 = (const float4*)hlin;
    float4 b4 = ((const float4*)bias)[lane];

    float4 s1 = make_float4(0.f, 0.f, 0.f, 0.f);
    float4 s2 = make_float4(0.f, 0.f, 0.f, 0.f);

    for (int n = gw; n < NN; n += nw) {
        int beg = g_rowptr[n], end = g_rowptr[n + 1];
        float4 acc = make_float4(0.f, 0.f, 0.f, 0.f);
        int e = beg;
        while (e < end) {
            int m2 = end - e; if (m2 > 8) m2 = 8;
            int   cc[8];
            float ww[8];
#pragma unroll
            for (int j = 0; j < 8; j++)
                if (j < m2) { cc[j] = g_col[e + j]; ww[j] = g_wgt[e + j]; }
#pragma unroll
            for (int j = 0; j < 8; j++)
                if (j < m2) {
                    float4 v = h4[(size_t)cc[j] * 32 + lane];
                    float w = ww[j];
                    acc.x += v.x * w; acc.y += v.y * w;
                    acc.z += v.z * w; acc.w += v.w * w;
                }
            e += m2;
        }
        float sw = g_selfw[n];
        float4 sf = h4[(size_t)n * 32 + lane];
        float4 o;
        o.x = acc.x + sf.x * sw + b4.x;
        o.y = acc.y + sf.y * sw + b4.y;
        o.z = acc.z + sf.z * sw + b4.z;
        o.w = acc.w + sf.w * sw + b4.w;
        ((float4*)hout)[(size_t)n * 32 + lane] = o;
        if (do_stats) {
            s1.x += o.x; s1.y += o.y; s1.z += o.z; s1.w += o.w;
            s2.x += o.x * o.x; s2.y += o.y * o.y;
            s2.z += o.z * o.z; s2.w += o.w * o.w;
        }
    }

    if (do_stats) {
        __shared__ float red[8][2 * HH];
        float* r = red[warp];
        int c = lane * 4;
        r[c] = s1.x; r[c + 1] = s1.y; r[c + 2] = s1.z; r[c + 3] = s1.w;
        r[HH + c] = s2.x; r[HH + c + 1] = s2.y;
        r[HH + c + 2] = s2.z; r[HH + c + 3] = s2.w;
        __syncthreads();
        int t = threadIdx.x;
        float s = 0.f;
#pragma unroll
        for (int w2 = 0; w2 < 8; w2++) s += red[w2][t];
        atomicAdd(&stats[t], s);
    }
}

// ---------------- global mean pool (batch sorted) ---------------------------
__device__ __forceinline__ int lowerb(const int* a, int n, int key) {
    int lo = 0, hi = n;
    while (lo < hi) {
        int m = (lo + hi) >> 1;
        if (a[m] < key) lo = m + 1; else hi = m;
    }
    return lo;
}

__global__ void k_pool(const float* __restrict__ h, const int* __restrict__ batch) {
    __shared__ float red[4][HH];
    int g = blockIdx.x;
    int c = threadIdx.x & 127;
    int sub = threadIdx.x >> 7;
    int lo = lowerb(batch, NN, g);
    int hi = lowerb(batch, NN, g + 1);
    float s = 0.f;
    for (int i = lo + sub; i < hi; i += 4) s += h[(size_t)i * HH + c];
    red[sub][c] = s;
    __syncthreads();
    if (sub == 0) {
        float tot = red[0][c] + red[1][c] + red[2][c] + red[3][c];
        int cnt = hi - lo;
        g_pooled[g * HH + c] = tot / (float)(cnt > 0 ? cnt : 1);
    }
}

// ---------------- prediction head -------------------------------------------
__global__ void k_head_gemm(const float* __restrict__ X, const float* __restrict__ W,
                            const float* __restrict__ b, float* __restrict__ Y,
                            int relu) {
    __shared__ float xs[HH];
    int g = blockIdx.x, c = threadIdx.x;
    xs[c] = X[g * HH + c];
    __syncthreads();
    float acc = b[c];
#pragma unroll
    for (int k = 0; k < HH; k++) acc += xs[k] * W[k * HH + c];
    if (relu) acc = fmaxf(acc, 0.f);
    Y[g * HH + c] = acc;
}

__global__ void k_headbn(const float* __restrict__ gamma, const float* __restrict__ beta) {
    int c = threadIdx.x;
    float s = 0.f, s2 = 0.f;
    for (int g = 0; g < GG; g++) {
        float v = g_z1[g * HH + c];
        s += v; s2 += v * v;
    }
    float mu = s / (float)GG;
    float var = s2 / (float)GG - mu * mu;
    float sc = rsqrtf(var + EPS) * gamma[c];
    float sh = beta[c] - mu * sc;
    for (int g = 0; g < GG; g++) {
        float v = g_z1[g * HH + c] * sc + sh;
        g_z1[g * HH + c] = fmaxf(v, 0.f);
    }
}

__global__ void k_head_out(const float* __restrict__ X, const float* __restrict__ W,
                           const float* __restrict__ b, float* __restrict__ Y) {
    __shared__ float xs[HH];
    int g = blockIdx.x, t = threadIdx.x;
    for (int i = t; i < HH; i += 32) xs[i] = X[g * HH + i];
    __syncthreads();
    if (t < OUTC) {
        float acc = b[t];
#pragma unroll
        for (int k = 0; k < HH; k++) acc += xs[k] * W[k * OUTC + t];
        Y[g * OUTC + t] = acc;
    }
}

// ---------------- launch ----------------------------------------------------
extern "C" void kernel_launch(void* const* d_in, const int* in_sizes, int n_in,
                              void* d_out, int out_size) {
    const float* x        = (const float*)d_in[0];
    const int*   eidx     = (const int*)  d_in[1];
    const int*   batch    = (const int*)  d_in[2];
    const float* conv_W   = (const float*)d_in[3];
    const float* conv_b   = (const float*)d_in[4];
    const float* bn_gamma = (const float*)d_in[5];
    const float* bn_beta  = (const float*)d_in[6];
    const float* head_W1  = (const float*)d_in[7];
    const float* head_b1  = (const float*)d_in[8];
    const float* head_bng = (const float*)d_in[9];
    const float* head_bnb = (const float*)d_in[10];
    const float* head_W2  = (const float*)d_in[11];
    const float* head_b2  = (const float*)d_in[12];
    const float* head_W3  = (const float*)d_in[13];
    const float* head_b3  = (const float*)d_in[14];
    float* out = (float*)d_out;

    const int* src = eidx;
    const int* dst = eidx + EE;

    float *buf, *lin, *pooled, *z1, *z2, *stats;
    cudaGetSymbolAddress((void**)&buf,    g_buf);
    cudaGetSymbolAddress((void**)&lin,    g_lin);
    cudaGetSymbolAddress((void**)&pooled, g_pooled);
    cudaGetSymbolAddress((void**)&z1,     g_z1);
    cudaGetSymbolAddress((void**)&z2,     g_z2);
    cudaGetSymbolAddress((void**)&stats,  g_stats);

    cudaFuncSetAttribute(k_gemm, cudaFuncAttributeMaxDynamicSharedMemorySize, SMEM_TC);

    // one side stream + fork/join events (created once; host-side only)
    static cudaStream_t s2 = nullptr;
    static cudaEvent_t evRoot = nullptr, evJoin = nullptr;
    if (!s2) {
        cudaStreamCreateWithFlags(&s2, cudaStreamNonBlocking);
        cudaEventCreateWithFlags(&evRoot, cudaEventDisableTiming);
        cudaEventCreateWithFlags(&evJoin, cudaEventDisableTiming);
    }

    // --- fork: graph preprocessing on s2, GEMM L0 on main (independent) ---
    cudaEventRecord(evRoot, 0);
    cudaStreamWaitEvent(s2, evRoot, 0);

    k_zero_counts<<<(NN + 511) / 512, 512, 0, s2>>>();            // launch 1
    k_hist<<<(EE + 255) / 256, 256, 0, s2>>>(dst);                // launch 2
    k_scan_local<<<NPART, 512, 0, s2>>>();                        // launch 3
    k_gemm<<<GEMM_GRID, 256, SMEM_TC>>>(x, conv_W, lin,           // launch 4 (profiled)
                                        nullptr, nullptr, nullptr, 0);
    k_scan_part<<<1, 128, 0, s2>>>();                             // launch 5
    k_scan_add<<<(NN + 511) / 512, 512, 0, s2>>>();               // launch 6
    k_dinv<<<(NN + 255) / 256, 256, 0, s2>>>();                   // launch 7
    k_scatter<<<(EE + 255) / 256, 256, 0, s2>>>(src, dst);        // launch 8

    cudaEventRecord(evJoin, s2);
    cudaStreamWaitEvent(0, evJoin, 0);

    // --- GCN layers (L0 GEMM already issued above) ---
    k_agg<<<1024, 256>>>(lin, conv_b, buf, stats, 1);
    for (int l = 1; l < LL; l++) {
        const float* st_in = stats + (l - 1) * 2 * HH;
        const float* ga = bn_gamma + (l - 1) * HH;
        const float* be = bn_beta + (l - 1) * HH;
        k_gemm<<<GEMM_GRID, 256, SMEM_TC>>>(buf, conv_W + l * HH * HH, lin,
                                            st_in, ga, be, 1);
        float* st_out = (l < LL - 1) ? stats + l * 2 * HH : nullptr;
        k_agg<<<1024, 256>>>(lin, conv_b + l * HH, buf, st_out, l < LL - 1 ? 1 : 0);
    }

    // --- pool + head ---
    k_pool<<<GG, 512>>>(buf, batch);
    k_head_gemm<<<GG, HH>>>(pooled, head_W1, head_b1, z1, 0);
    k_headbn<<<1, HH>>>(head_bng, head_bnb);
    k_head_gemm<<<GG, HH>>>(z1, head_W2, head_b2, z2, 1);
    k_head_out<<<GG, 32>>>(z2, head_W3, head_b3, out);
}

// round 12
// speedup vs baseline: 1.0473x; 1.0473x over previous
#include <cuda_runtime.h>
#include <cuda_bf16.h>
#include <math.h>
#include <cstdint>

#define NN   50000
#define EE   800000
#define HH   128
#define GG   64
#define LL   6
#define OUTC 10
#define EPS  1e-5f
#define NPART 98            // ceil(NN/512)
#define TILES ((NN + 63) / 64)
#define GEMM_GRID 148       // 1 CTA/SM persistent
#define BP   136            // bf16 smem pitch (272B rows)

typedef unsigned long long ull;

// ---------------- scratch (device globals) ----------------------------------
__device__ float g_buf [NN * HH];
__device__ float g_lin [NN * HH];
__device__ int   g_cnt [NN];
__device__ int   g_cur [NN];
__device__ int   g_rowptr[NN + 1];
__device__ int   g_part[NPART];
__device__ int   g_col [EE];
__device__ float g_wgt [EE];
__device__ float g_dinv[NN];
__device__ float g_selfw[NN];
__device__ float g_stats[(LL - 1) * 2 * HH];
__device__ float g_pooled[GG * HH];
__device__ float g_z1[GG * HH];
__device__ float g_z2[GG * HH];

// ---------------- mma / ldmatrix helpers -------------------------------------
__device__ __forceinline__ uint32_t smem_u32(const void* p) {
    uint32_t a;
    asm("{ .reg .u64 t; cvta.to.shared.u64 t, %1; cvt.u32.u64 %0, t; }" : "=r"(a) : "l"(p));
    return a;
}
__device__ __forceinline__ void ldmx4(uint32_t& r0, uint32_t& r1, uint32_t& r2,
                                      uint32_t& r3, uint32_t a) {
    asm volatile("ldmatrix.sync.aligned.m8n8.x4.shared.b16 {%0,%1,%2,%3}, [%4];"
                 : "=r"(r0), "=r"(r1), "=r"(r2), "=r"(r3) : "r"(a));
}
__device__ __forceinline__ void mma_bf16(float* c, const uint32_t* a,
                                         uint32_t b0, uint32_t b1) {
    asm volatile("mma.sync.aligned.m16n8k16.row.col.f32.bf16.bf16.f32 "
                 "{%0,%1,%2,%3}, {%4,%5,%6,%7}, {%8,%9}, {%0,%1,%2,%3};"
                 : "+f"(c[0]), "+f"(c[1]), "+f"(c[2]), "+f"(c[3])
                 : "r"(a[0]), "r"(a[1]), "r"(a[2]), "r"(a[3]), "r"(b0), "r"(b1));
}
__device__ __forceinline__ uint32_t pack_hi(float x, float y) {
    __nv_bfloat162 h(__float2bfloat16_rn(x), __float2bfloat16_rn(y));
    return *(uint32_t*)&h;
}
__device__ __forceinline__ uint32_t pack_lo(float x, float y) {
    __nv_bfloat16 hx = __float2bfloat16_rn(x);
    __nv_bfloat16 hy = __float2bfloat16_rn(y);
    __nv_bfloat162 l(__float2bfloat16_rn(x - __bfloat162float(hx)),
                     __float2bfloat16_rn(y - __bfloat162float(hy)));
    return *(uint32_t*)&l;
}

// ---------------- graph preprocessing ---------------------------------------
__global__ void k_zero_counts() {
    int i = blockIdx.x * blockDim.x + threadIdx.x;
    if (i < NN) { g_cnt[i] = 0; g_cur[i] = 0; }
    if (i < (LL - 1) * 2 * HH) g_stats[i] = 0.f;
}

__global__ void k_hist(const int* __restrict__ dst) {
    int i = blockIdx.x * blockDim.x + threadIdx.x;
    if (i < EE) atomicAdd(&g_cnt[dst[i]], 1);
}

__global__ void k_scan_local() {
    __shared__ int sh[512];
    int t = threadIdx.x;
    int i = blockIdx.x * 512 + t;
    int v = (i < NN) ? g_cnt[i] : 0;
    sh[t] = v;
    __syncthreads();
    for (int off = 1; off < 512; off <<= 1) {
        int a = (t >= off) ? sh[t - off] : 0;
        __syncthreads();
        sh[t] += a;
        __syncthreads();
    }
    if (i < NN) g_rowptr[i + 1] = sh[t];
    if (t == 511) g_part[blockIdx.x] = sh[t];
}

__global__ void k_scan_part() {
    __shared__ int sh[128];
    int t = threadIdx.x;
    int v = (t < NPART) ? g_part[t] : 0;
    sh[t] = v;
    __syncthreads();
    for (int off = 1; off < 128; off <<= 1) {
        int a = (t >= off) ? sh[t - off] : 0;
        __syncthreads();
        sh[t] += a;
        __syncthreads();
    }
    if (t < NPART) g_part[t] = sh[t] - v;   // exclusive
}

__global__ void k_scan_add() {
    int i = blockIdx.x * blockDim.x + threadIdx.x;
    if (i < NN) g_rowptr[i + 1] += g_part[i >> 9];
    if (i == 0) g_rowptr[0] = 0;
}

__global__ void k_dinv() {
    int i = blockIdx.x * blockDim.x + threadIdx.x;
    if (i < NN) {
        float deg = (float)(g_cnt[i] + 1);
        g_dinv[i] = rsqrtf(deg);
        g_selfw[i] = 1.f / deg;
    }
}

__global__ void k_scatter(const int* __restrict__ src, const int* __restrict__ dst) {
    int i = blockIdx.x * blockDim.x + threadIdx.x;
    if (i < EE) {
        int s = src[i], d = dst[i];
        int p = atomicAdd(&g_cur[d], 1);
        int idx = g_rowptr[d] + p;
        g_col[idx] = s;
        g_wgt[idx] = g_dinv[s] * g_dinv[d];
    }
}

// ---------------- tensor-core GEMM: Y = act(X) @ W ---------------------------
// mma.sync m16n8k16 bf16, 3-pass split. Warp = 32 rows x 32 cols; B fragments
// register-resident for the CTA lifetime. X rows for the NEXT tile are
// prefetched into registers (8 float4/thread) so the per-tile fill is pure
// BN+pack+STS with no exposed LDG latency.
#define SM_BHI  0
#define SM_BLO  (SM_BHI + HH * BP * 2)
#define SM_XHI  (SM_BLO + HH * BP * 2)
#define SM_XLO  (SM_XHI + 64 * BP * 2)
#define SM_SC   (SM_XLO + 64 * BP * 2)
#define SM_SH   (SM_SC + 512)
#define SMEM_TC (SM_SH + 512)

__global__ __launch_bounds__(256, 1)
void k_gemm(const float* __restrict__ X, const float* __restrict__ W,
            float* __restrict__ Y,
            const float* __restrict__ stats,
            const float* __restrict__ gamma, const float* __restrict__ beta,
            int bn) {
    extern __shared__ char smem[];
    __nv_bfloat16* Bh = (__nv_bfloat16*)(smem + SM_BHI);
    __nv_bfloat16* Bl = (__nv_bfloat16*)(smem + SM_BLO);
    float* sc = (float*)(smem + SM_SC);
    float* shf = (float*)(smem + SM_SH);

    int tid = threadIdx.x;
    int lr = tid >> 2;                    // fill row 0..63
    int kq0 = tid & 3;                    // fill float4 phase

    // ---- prefetch first tile into registers ----
    float4 pf[8];
    {
        int grow = blockIdx.x * 64 + lr;
        bool rv = grow < NN;
        const float4* Xg = (const float4*)(X + (size_t)(rv ? grow : 0) * HH);
#pragma unroll
        for (int i = 0; i < 8; i++)
            pf[i] = rv ? Xg[kq0 + i * 4] : make_float4(0.f, 0.f, 0.f, 0.f);
    }

    if (bn && tid < HH) {
        float mu  = stats[tid] * (1.f / NN);
        float var = stats[HH + tid] * (1.f / NN) - mu * mu;
        float s = rsqrtf(var + EPS) * gamma[tid];
        sc[tid] = s;
        shf[tid] = beta[tid] - mu * s;
    }

    {   // split W into Bt[n][k] hi/lo (once per CTA)
        const float4* W4 = (const float4*)W;
        for (int i = tid; i < HH * 32; i += 256) {
            int k = i >> 5, n4 = i & 31;
            float4 v = W4[k * 32 + n4];
            const float* vv = (const float*)&v;
#pragma unroll
            for (int j = 0; j < 4; j++) {
                int n = n4 * 4 + j;
                __nv_bfloat16 hi = __float2bfloat16_rn(vv[j]);
                Bh[n * BP + k] = hi;
                Bl[n * BP + k] = __float2bfloat16_rn(vv[j] - __bfloat162float(hi));
            }
        }
    }
    __syncthreads();

    uint32_t xh_u = smem_u32(smem + SM_XHI);
    uint32_t xl_u = smem_u32(smem + SM_XLO);
    uint32_t bh_u = smem_u32(smem + SM_BHI);
    uint32_t bl_u = smem_u32(smem + SM_BLO);

    int warp = tid >> 5, lane = tid & 31;
    int mrow = (warp & 1) * 32;
    int ncol = (warp >> 1) * 32;

    int aj = lane >> 3, ar = lane & 7;
    int a_rb  = ((aj & 1) << 3) + ar;
    int a_kad = (aj >> 1) << 3;
    int b_rowoff = ((aj >> 1) << 3) + ar;
    int b_kad = (aj & 1) << 3;

    // ---- preload ALL B fragments for this warp's 32 cols ----
    uint32_t bhr[8][2][4], blr[8][2][4];
#pragma unroll
    for (int ks = 0; ks < 8; ks++)
#pragma unroll
        for (int ng = 0; ng < 2; ng++) {
            int n0 = ncol + 16 * ng;
            uint32_t boff = (uint32_t)(((n0 + b_rowoff) * BP + ks * 16 + b_kad) * 2);
            ldmx4(bhr[ks][ng][0], bhr[ks][ng][1], bhr[ks][ng][2], bhr[ks][ng][3], bh_u + boff);
            ldmx4(blr[ks][ng][0], blr[ks][ng][1], blr[ks][ng][2], blr[ks][ng][3], bl_u + boff);
        }

    for (int tile = blockIdx.x; tile < TILES; tile += gridDim.x) {
        int row0 = tile * 64;

        {   // fill X hi/lo tiles from prefetched registers (BN/ReLU fused)
#pragma unroll
            for (int i = 0; i < 8; i++) {
                int m = kq0 + i * 4;
                float4 v = pf[i];
                if (bn) {
                    int ch = 4 * m;
                    v.x = fmaxf(v.x * sc[ch]     + shf[ch],     0.f);
                    v.y = fmaxf(v.y * sc[ch + 1] + shf[ch + 1], 0.f);
                    v.z = fmaxf(v.z * sc[ch + 2] + shf[ch + 2], 0.f);
                    v.w = fmaxf(v.w * sc[ch + 3] + shf[ch + 3], 0.f);
                }
                uint2 hp, lp;
                hp.x = pack_hi(v.x, v.y); hp.y = pack_hi(v.z, v.w);
                lp.x = pack_lo(v.x, v.y); lp.y = pack_lo(v.z, v.w);
                *(uint2*)(smem + SM_XHI + (lr * BP + 4 * m) * 2) = hp;
                *(uint2*)(smem + SM_XLO + (lr * BP + 4 * m) * 2) = lp;
            }
        }

        {   // issue prefetch LDGs for the NEXT tile (hidden behind the mma)
            int ntile = tile + gridDim.x;
            if (ntile < TILES) {
                int grow = ntile * 64 + lr;
                bool rv = grow < NN;
                const float4* Xg = (const float4*)(X + (size_t)(rv ? grow : 0) * HH);
#pragma unroll
                for (int i = 0; i < 8; i++)
                    pf[i] = rv ? Xg[kq0 + i * 4] : make_float4(0.f, 0.f, 0.f, 0.f);
            }
        }
        __syncthreads();

        float c[2][2][2][4];
#pragma unroll
        for (int mg = 0; mg < 2; mg++)
#pragma unroll
            for (int ng = 0; ng < 2; ng++)
#pragma unroll
                for (int nh = 0; nh < 2; nh++)
#pragma unroll
                    for (int j = 0; j < 4; j++) c[mg][ng][nh][j] = 0.f;

#pragma unroll
        for (int ks = 0; ks < 8; ks++) {
            int k0 = ks * 16;
#pragma unroll
            for (int mg = 0; mg < 2; mg++) {
                uint32_t ahi[4], alo[4];
                uint32_t aoff = (uint32_t)(((mrow + 16 * mg + a_rb) * BP + k0 + a_kad) * 2);
                ldmx4(ahi[0], ahi[1], ahi[2], ahi[3], xh_u + aoff);
                ldmx4(alo[0], alo[1], alo[2], alo[3], xl_u + aoff);
#pragma unroll
                for (int ng = 0; ng < 2; ng++) {
                    const uint32_t* bh = bhr[ks][ng];
                    const uint32_t* bl = blr[ks][ng];
                    mma_bf16(c[mg][ng][0], ahi, bh[0], bh[1]);
                    mma_bf16(c[mg][ng][0], alo, bh[0], bh[1]);
                    mma_bf16(c[mg][ng][0], ahi, bl[0], bl[1]);
                    mma_bf16(c[mg][ng][1], ahi, bh[2], bh[3]);
                    mma_bf16(c[mg][ng][1], alo, bh[2], bh[3]);
                    mma_bf16(c[mg][ng][1], ahi, bl[2], bl[3]);
                }
            }
        }

        {   // epilogue: c -> Y (fp32)
            int cb = 2 * (lane & 3);
            int rowin = lane >> 2;
#pragma unroll
            for (int mg = 0; mg < 2; mg++) {
                int m1 = row0 + mrow + 16 * mg + rowin;
                int m2 = m1 + 8;
                bool v1 = m1 < NN, v2 = m2 < NN;
#pragma unroll
                for (int ng = 0; ng < 2; ng++)
#pragma unroll
                    for (int nh = 0; nh < 2; nh++) {
                        int n0 = ncol + 16 * ng + 8 * nh + cb;
                        float* cc = c[mg][ng][nh];
                        if (v1) *(float2*)(Y + (size_t)m1 * HH + n0) = make_float2(cc[0], cc[1]);
                        if (v2) *(float2*)(Y + (size_t)m2 * HH + n0) = make_float2(cc[2], cc[3]);
                    }
            }
        }
        __syncthreads();   // X tile reuse barrier
    }
}

// ---------------- aggregation (fp32 gather) + fused BN stats -----------------
__global__ __launch_bounds__(256)
void k_agg(const float* __restrict__ hlin, const float* __restrict__ bias,
           float* __restrict__ hout, float* __restrict__ stats, int do_stats) {
    int lane = threadIdx.x & 31;
    int warp = threadIdx.x >> 5;
    int gw = blockIdx.x * 8 + warp;
    int nw = gridDim.x * 8;

    const float4* h4 = (const float4*)hlin;
    float4 b4 = ((const float4*)bias)[lane];

    float4 s1 = make_float4(0.f, 0.f, 0.f, 0.f);
    float4 s2 = make_float4(0.f, 0.f, 0.f, 0.f);

    for (int n = gw; n < NN; n += nw) {
        int beg = g_rowptr[n], end = g_rowptr[n + 1];
        float4 acc = make_float4(0.f, 0.f, 0.f, 0.f);
        int e = beg;
        while (e < end) {
            int m2 = end - e; if (m2 > 8) m2 = 8;
            int   cc[8];
            float ww[8];
#pragma unroll
            for (int j = 0; j < 8; j++)
                if (j < m2) { cc[j] = g_col[e + j]; ww[j] = g_wgt[e + j]; }
#pragma unroll
            for (int j = 0; j < 8; j++)
                if (j < m2) {
                    float4 v = h4[(size_t)cc[j] * 32 + lane];
                    float w = ww[j];
                    acc.x += v.x * w; acc.y += v.y * w;
                    acc.z += v.z * w; acc.w += v.w * w;
                }
            e += m2;
        }
        float sw = g_selfw[n];
        float4 sf = h4[(size_t)n * 32 + lane];
        float4 o;
        o.x = acc.x + sf.x * sw + b4.x;
        o.y = acc.y + sf.y * sw + b4.y;
        o.z = acc.z + sf.z * sw + b4.z;
        o.w = acc.w + sf.w * sw + b4.w;
        ((float4*)hout)[(size_t)n * 32 + lane] = o;
        if (do_stats) {
            s1.x += o.x; s1.y += o.y; s1.z += o.z; s1.w += o.w;
            s2.x += o.x * o.x; s2.y += o.y * o.y;
            s2.z += o.z * o.z; s2.w += o.w * o.w;
        }
    }

    if (do_stats) {
        __shared__ float red[8][2 * HH];
        float* r = red[warp];
        int c = lane * 4;
        r[c] = s1.x; r[c + 1] = s1.y; r[c + 2] = s1.z; r[c + 3] = s1.w;
        r[HH + c] = s2.x; r[HH + c + 1] = s2.y;
        r[HH + c + 2] = s2.z; r[HH + c + 3] = s2.w;
        __syncthreads();
        int t = threadIdx.x;
        float s = 0.f;
#pragma unroll
        for (int w2 = 0; w2 < 8; w2++) s += red[w2][t];
        atomicAdd(&stats[t], s);
    }
}

// ---------------- global mean pool (batch sorted) ---------------------------
__device__ __forceinline__ int lowerb(const int* a, int n, int key) {
    int lo = 0, hi = n;
    while (lo < hi) {
        int m = (lo + hi) >> 1;
        if (a[m] < key) lo = m + 1; else hi = m;
    }
    return lo;
}

__global__ void k_pool(const float* __restrict__ h, const int* __restrict__ batch) {
    __shared__ float red[4][HH];
    int g = blockIdx.x;
    int c = threadIdx.x & 127;
    int sub = threadIdx.x >> 7;
    int lo = lowerb(batch, NN, g);
    int hi = lowerb(batch, NN, g + 1);
    float s = 0.f;
    for (int i = lo + sub; i < hi; i += 4) s += h[(size_t)i * HH + c];
    red[sub][c] = s;
    __syncthreads();
    if (sub == 0) {
        float tot = red[0][c] + red[1][c] + red[2][c] + red[3][c];
        int cnt = hi - lo;
        g_pooled[g * HH + c] = tot / (float)(cnt > 0 ? cnt : 1);
    }
}

// ---------------- prediction head -------------------------------------------
__global__ void k_head_gemm(const float* __restrict__ X, const float* __restrict__ W,
                            const float* __restrict__ b, float* __restrict__ Y,
                            int relu) {
    __shared__ float xs[HH];
    int g = blockIdx.x, c = threadIdx.x;
    xs[c] = X[g * HH + c];
    __syncthreads();
    float acc = b[c];
#pragma unroll
    for (int k = 0; k < HH; k++) acc += xs[k] * W[k * HH + c];
    if (relu) acc = fmaxf(acc, 0.f);
    Y[g * HH + c] = acc;
}

__global__ void k_headbn(const float* __restrict__ gamma, const float* __restrict__ beta) {
    int c = threadIdx.x;
    float s = 0.f, s2 = 0.f;
    for (int g = 0; g < GG; g++) {
        float v = g_z1[g * HH + c];
        s += v; s2 += v * v;
    }
    float mu = s / (float)GG;
    float var = s2 / (float)GG - mu * mu;
    float sc = rsqrtf(var + EPS) * gamma[c];
    float sh = beta[c] - mu * sc;
    for (int g = 0; g < GG; g++) {
        float v = g_z1[g * HH + c] * sc + sh;
        g_z1[g * HH + c] = fmaxf(v, 0.f);
    }
}

__global__ void k_head_out(const float* __restrict__ X, const float* __restrict__ W,
                           const float* __restrict__ b, float* __restrict__ Y) {
    __shared__ float xs[HH];
    int g = blockIdx.x, t = threadIdx.x;
    for (int i = t; i < HH; i += 32) xs[i] = X[g * HH + i];
    __syncthreads();
    if (t < OUTC) {
        float acc = b[t];
#pragma unroll
        for (int k = 0; k < HH; k++) acc += xs[k] * W[k * OUTC + t];
        Y[g * OUTC + t] = acc;
    }
}

// ---------------- launch ----------------------------------------------------
extern "C" void kernel_launch(void* const* d_in, const int* in_sizes, int n_in,
                              void* d_out, int out_size) {
    const float* x        = (const float*)d_in[0];
    const int*   eidx     = (const int*)  d_in[1];
    const int*   batch    = (const int*)  d_in[2];
    const float* conv_W   = (const float*)d_in[3];
    const float* conv_b   = (const float*)d_in[4];
    const float* bn_gamma = (const float*)d_in[5];
    const float* bn_beta  = (const float*)d_in[6];
    const float* head_W1  = (const float*)d_in[7];
    const float* head_b1  = (const float*)d_in[8];
    const float* head_bng = (const float*)d_in[9];
    const float* head_bnb = (const float*)d_in[10];
    const float* head_W2  = (const float*)d_in[11];
    const float* head_b2  = (const float*)d_in[12];
    const float* head_W3  = (const float*)d_in[13];
    const float* head_b3  = (const float*)d_in[14];
    float* out = (float*)d_out;

    const int* src = eidx;
    const int* dst = eidx + EE;

    float *buf, *lin, *pooled, *z1, *z2, *stats;
    cudaGetSymbolAddress((void**)&buf,    g_buf);
    cudaGetSymbolAddress((void**)&lin,    g_lin);
    cudaGetSymbolAddress((void**)&pooled, g_pooled);
    cudaGetSymbolAddress((void**)&z1,     g_z1);
    cudaGetSymbolAddress((void**)&z2,     g_z2);
    cudaGetSymbolAddress((void**)&stats,  g_stats);

    cudaFuncSetAttribute(k_gemm, cudaFuncAttributeMaxDynamicSharedMemorySize, SMEM_TC);

    // one side stream + fork/join events (created once; host-side only)
    static cudaStream_t s2 = nullptr;
    static cudaEvent_t evRoot = nullptr, evJoin = nullptr;
    if (!s2) {
        cudaStreamCreateWithFlags(&s2, cudaStreamNonBlocking);
        cudaEventCreateWithFlags(&evRoot, cudaEventDisableTiming);
        cudaEventCreateWithFlags(&evJoin, cudaEventDisableTiming);
    }

    // --- fork: graph preprocessing on s2, GEMM L0 on main (independent) ---
    cudaEventRecord(evRoot, 0);
    cudaStreamWaitEvent(s2, evRoot, 0);

    k_zero_counts<<<(NN + 511) / 512, 512, 0, s2>>>();            // launch 1
    k_hist<<<(EE + 255) / 256, 256, 0, s2>>>(dst);                // launch 2
    k_scan_local<<<NPART, 512, 0, s2>>>();                        // launch 3
    k_gemm<<<GEMM_GRID, 256, SMEM_TC>>>(x, conv_W, lin,           // launch 4 (profiled)
                                        nullptr, nullptr, nullptr, 0);
    k_scan_part<<<1, 128, 0, s2>>>();                             // launch 5
    k_scan_add<<<(NN + 511) / 512, 512, 0, s2>>>();               // launch 6
    k_dinv<<<(NN + 255) / 256, 256, 0, s2>>>();                   // launch 7
    k_scatter<<<(EE + 255) / 256, 256, 0, s2>>>(src, dst);        // launch 8

    cudaEventRecord(evJoin, s2);
    cudaStreamWaitEvent(0, evJoin, 0);

    // --- GCN layers (L0 GEMM already issued above) ---
    k_agg<<<1024, 256>>>(lin, conv_b, buf, stats, 1);
    for (int l = 1; l < LL; l++) {
        const float* st_in = stats + (l - 1) * 2 * HH;
        const float* ga = bn_gamma + (l - 1) * HH;
        const float* be = bn_beta + (l - 1) * HH;
        k_gemm<<<GEMM_GRID, 256, SMEM_TC>>>(buf, conv_W + l * HH * HH, lin,
                                            st_in, ga, be, 1);
        float* st_out = (l < LL - 1) ? stats + l * 2 * HH : nullptr;
        k_agg<<<1024, 256>>>(lin, conv_b + l * HH, buf, st_out, l < LL - 1 ? 1 : 0);
    }

    // --- pool + head ---
    k_pool<<<GG, 512>>>(buf, batch);
    k_head_gemm<<<GG, HH>>>(pooled, head_W1, head_b1, z1, 0);
    k_headbn<<<1, HH>>>(head_bng, head_bnb);
    k_head_gemm<<<GG, HH>>>(z1, head_W2, head_b2, z2, 1);
    k_head_out<<<GG, 32>>>(z2, head_W3, head_b3, out);
}